// round 4
// baseline (speedup 1.0000x reference)
#include <cuda_runtime.h>
#include <cuda_bf16.h>
#include <cstdint>

// ---------------- problem constants ----------------
#define NND   20000          // nodes
#define EE    320000         // edges
#define ET    340000         // edges + self loops
#define EL    100000         // label edges
#define DIN   256
#define DHID  128
#define DOUT  128
#define NH    4
#define D1    512            // NH*DHID
#define NEG   0.2f

// ---------------- device scratch (16B-aligned for float4 / red.v4) ----------
__device__ __align__(16) float g_xl1[NND * D1];
__device__ __align__(16) float g_xr1[NND * D1];
__device__ __align__(16) float g_out1[NND * D1];   // layer-1 aggregate
__device__ __align__(16) float g_x2[NND * D1];     // gelu(out1 + bias1)
__device__ __align__(16) float g_xl2[NND * DOUT];
__device__ __align__(16) float g_xr2[NND * DOUT];
__device__ __align__(16) float g_z2[NND * DOUT];
__device__ __align__(16) float g_logits1[ET * NH];
__device__ __align__(16) float g_logits2[ET];
__device__ __align__(16) float g_m1[NND * NH];
__device__ __align__(16) float g_s1[NND * NH];
__device__ __align__(16) float g_m2[NND];
__device__ __align__(16) float g_s2[NND];

// ---------------- helpers ----------------
__device__ __forceinline__ float4 ld4(const float* p) {
    return *reinterpret_cast<const float4*>(p);
}

__device__ __forceinline__ void redAdd4(float* p, float4 v) {
    asm volatile("red.global.add.v4.f32 [%0], {%1,%2,%3,%4};"
                 :: "l"(p), "f"(v.x), "f"(v.y), "f"(v.z), "f"(v.w) : "memory");
}

// float atomic max via int/uint ordering trick. Init bit pattern 0xFFFFFFFF:
// as int = -1 (< any non-negative float's bits), as uint = UINT_MAX (> any
// negative float's bits) -> first real value always wins.
__device__ __forceinline__ void atomicMaxFloat(float* addr, float v) {
    if (__float_as_int(v) >= 0) {
        atomicMax(reinterpret_cast<int*>(addr), __float_as_int(v));
    } else {
        atomicMin(reinterpret_cast<unsigned int*>(addr), __float_as_uint(v));
    }
}

__device__ __forceinline__ float gelu_tanh(float x) {
    float x3 = x * x * x;
    float t = tanhf(0.7978845608028654f * (x + 0.044715f * x3));
    return 0.5f * x * (1.0f + t);
}

__device__ __forceinline__ float lrelu(float x) {
    return x > 0.0f ? x : NEG * x;
}

// ---------------- init (kernels-only) ----------------
__global__ void init_kernel() {
    int i = blockIdx.x * blockDim.x + threadIdx.x;
    if (i < NND * D1)   g_out1[i] = 0.0f;
    if (i < NND * DOUT) g_z2[i]   = 0.0f;
    if (i < NND * NH) { g_s1[i] = 0.0f; g_m1[i] = __uint_as_float(0xFFFFFFFFu); }
    if (i < NND)      { g_s2[i] = 0.0f; g_m2[i] = __uint_as_float(0xFFFFFFFFu); }
}

// ---------------- scratch selectors (resolved IN DEVICE CODE) --------------
// ASEL: -1 = use parameter A, 2 = g_x2
// CSEL:  0 = g_xl1, 1 = g_xr1, 3 = g_xl2, 4 = g_xr2
template<int SEL>
__device__ __forceinline__ const float* a_sel(const float* A) {
    if constexpr (SEL == 2) return g_x2;
    else return A;
}
template<int SEL>
__device__ __forceinline__ float* c_sel() {
    if constexpr (SEL == 0) return g_xl1;
    else if constexpr (SEL == 1) return g_xr1;
    else if constexpr (SEL == 3) return g_xl2;
    else return g_xr2;
}

// ---------------- SGEMM: C[M,N] = A[M,K] @ B[K,N] + bias[N] ----------------
// BM=128, BN=64, BK=16, 256 threads, 8x4 per thread.
template<int BM, int BN, int BK, int TM, int TN, int ASEL, int CSEL>
__global__ void sgemm_bias_kernel(const float* __restrict__ Ain,
                                  const float* __restrict__ B,
                                  const float* __restrict__ bias,
                                  int M, int N, int K) {
    constexpr int THREADS = (BM * BN) / (TM * TN);   // 256
    const float* __restrict__ A = a_sel<ASEL>(Ain);
    float* __restrict__ C = c_sel<CSEL>();

    __shared__ float As[BK][BM + 4];
    __shared__ float Bs[BK][BN];

    const int tid = threadIdx.x;
    const int tx = tid % (BN / TN);   // 16
    const int ty = tid / (BN / TN);   // 16
    const int rowBase = blockIdx.y * BM;
    const int colBase = blockIdx.x * BN;

    float acc[TM][TN];
    #pragma unroll
    for (int i = 0; i < TM; i++)
        #pragma unroll
        for (int j = 0; j < TN; j++) acc[i][j] = 0.0f;

    for (int kk = 0; kk < K; kk += BK) {
        #pragma unroll
        for (int it = 0; it < (BM * BK) / (4 * THREADS); ++it) {
            int idx = tid + it * THREADS;
            int ar  = idx / (BK / 4);
            int akv = idx % (BK / 4);
            int grow = rowBase + ar;
            float4 v = (grow < M) ? ld4(A + (size_t)grow * K + kk + akv * 4)
                                  : make_float4(0.f, 0.f, 0.f, 0.f);
            As[akv * 4 + 0][ar] = v.x;
            As[akv * 4 + 1][ar] = v.y;
            As[akv * 4 + 2][ar] = v.z;
            As[akv * 4 + 3][ar] = v.w;
        }
        #pragma unroll
        for (int it = 0; it < (BK * BN) / (4 * THREADS); ++it) {
            int idx = tid + it * THREADS;
            int br  = idx / (BN / 4);
            int bcv = idx % (BN / 4);
            *reinterpret_cast<float4*>(&Bs[br][bcv * 4]) =
                ld4(B + (size_t)(kk + br) * N + colBase + bcv * 4);
        }
        __syncthreads();

        #pragma unroll
        for (int k = 0; k < BK; ++k) {
            float4 ra0 = *reinterpret_cast<const float4*>(&As[k][ty * TM]);
            float4 ra1 = *reinterpret_cast<const float4*>(&As[k][ty * TM + 4]);
            float4 rb  = *reinterpret_cast<const float4*>(&Bs[k][tx * TN]);
            float ra[TM] = {ra0.x, ra0.y, ra0.z, ra0.w, ra1.x, ra1.y, ra1.z, ra1.w};
            float rbv[TN] = {rb.x, rb.y, rb.z, rb.w};
            #pragma unroll
            for (int i = 0; i < TM; i++)
                #pragma unroll
                for (int j = 0; j < TN; j++)
                    acc[i][j] = fmaf(ra[i], rbv[j], acc[i][j]);
        }
        __syncthreads();
    }

    float4 bv = ld4(bias + colBase + tx * TN);
    #pragma unroll
    for (int i = 0; i < TM; i++) {
        int r = rowBase + ty * TM + i;
        if (r < M) {
            float4 o = make_float4(acc[i][0] + bv.x, acc[i][1] + bv.y,
                                   acc[i][2] + bv.z, acc[i][3] + bv.w);
            *reinterpret_cast<float4*>(C + (size_t)r * N + colBase + tx * TN) = o;
        }
    }
}

// ---------------- layer 1 edge kernels (H=4, C=128) ----------------
// warp per edge; lane handles 16 contiguous floats (8 lanes per head)
__global__ void logits1_kernel(const int* __restrict__ ei,
                               const float* __restrict__ att) {
    int w = (blockIdx.x * blockDim.x + threadIdx.x) >> 5;
    int lane = threadIdx.x & 31;
    if (w >= ET) return;
    int src, dst;
    if (w < EE) { src = ei[w]; dst = ei[EE + w]; }
    else        { src = dst = w - EE; }

    const float4* pa = reinterpret_cast<const float4*>(g_xl1 + (size_t)src * D1) + lane * 4;
    const float4* pb = reinterpret_cast<const float4*>(g_xr1 + (size_t)dst * D1) + lane * 4;
    const float4* pt = reinterpret_cast<const float4*>(att) + lane * 4;

    float p = 0.0f;
    #pragma unroll
    for (int i = 0; i < 4; i++) {
        float4 a = pa[i], b = pb[i], t = pt[i];
        p = fmaf(lrelu(a.x + b.x), t.x, p);
        p = fmaf(lrelu(a.y + b.y), t.y, p);
        p = fmaf(lrelu(a.z + b.z), t.z, p);
        p = fmaf(lrelu(a.w + b.w), t.w, p);
    }
    p += __shfl_xor_sync(0xffffffffu, p, 4);
    p += __shfl_xor_sync(0xffffffffu, p, 2);
    p += __shfl_xor_sync(0xffffffffu, p, 1);
    if ((lane & 7) == 0) {
        int h = lane >> 3;
        g_logits1[w * NH + h] = p;
        atomicMaxFloat(g_m1 + dst * NH + h, p);
    }
}

__global__ void expsum1_kernel(const int* __restrict__ ei) {
    int e = blockIdx.x * blockDim.x + threadIdx.x;
    if (e >= ET) return;
    int dst = (e < EE) ? ei[EE + e] : e - EE;
    float4 lg = reinterpret_cast<float4*>(g_logits1)[e];
    float4 mm = reinterpret_cast<const float4*>(g_m1)[dst];
    float4 a;
    a.x = expf(lg.x - mm.x);
    a.y = expf(lg.y - mm.y);
    a.z = expf(lg.z - mm.z);
    a.w = expf(lg.w - mm.w);
    reinterpret_cast<float4*>(g_logits1)[e] = a;
    redAdd4(g_s1 + dst * NH, a);
}

__global__ void aggregate1_kernel(const int* __restrict__ ei) {
    int w = (blockIdx.x * blockDim.x + threadIdx.x) >> 5;
    int lane = threadIdx.x & 31;
    if (w >= ET) return;
    int src, dst;
    if (w < EE) { src = ei[w]; dst = ei[EE + w]; }
    else        { src = dst = w - EE; }

    float4 a = reinterpret_cast<const float4*>(g_logits1)[w];
    float4 s = reinterpret_cast<const float4*>(g_s1)[dst];
    float al0 = a.x / s.x, al1 = a.y / s.y, al2 = a.z / s.z, al3 = a.w / s.w;
    int h = lane >> 3;
    float scale = (h < 2) ? (h == 0 ? al0 : al1) : (h == 2 ? al2 : al3);

    const float4* px = reinterpret_cast<const float4*>(g_xl1 + (size_t)src * D1) + lane * 4;
    float* po = g_out1 + (size_t)dst * D1 + lane * 16;
    #pragma unroll
    for (int i = 0; i < 4; i++) {
        float4 v = px[i];
        v.x *= scale; v.y *= scale; v.z *= scale; v.w *= scale;
        redAdd4(po + i * 4, v);
    }
}

// g_x2 = gelu(g_out1 + bias1)
__global__ void gelu_bias_kernel(const float* __restrict__ bias) {
    int i4 = blockIdx.x * blockDim.x + threadIdx.x;
    const int total4 = NND * D1 / 4;
    if (i4 >= total4) return;
    float4 v = reinterpret_cast<const float4*>(g_out1)[i4];
    float4 b = reinterpret_cast<const float4*>(bias)[i4 % (D1 / 4)];
    float4 o;
    o.x = gelu_tanh(v.x + b.x);
    o.y = gelu_tanh(v.y + b.y);
    o.z = gelu_tanh(v.z + b.z);
    o.w = gelu_tanh(v.w + b.w);
    reinterpret_cast<float4*>(g_x2)[i4] = o;
}

// ---------------- layer 2 edge kernels (H=1, C=128) ----------------
__global__ void logits2_kernel(const int* __restrict__ ei,
                               const float* __restrict__ att) {
    int w = (blockIdx.x * blockDim.x + threadIdx.x) >> 5;
    int lane = threadIdx.x & 31;
    if (w >= ET) return;
    int src, dst;
    if (w < EE) { src = ei[w]; dst = ei[EE + w]; }
    else        { src = dst = w - EE; }

    float4 a = reinterpret_cast<const float4*>(g_xl2 + (size_t)src * DOUT)[lane];
    float4 b = reinterpret_cast<const float4*>(g_xr2 + (size_t)dst * DOUT)[lane];
    float4 t = reinterpret_cast<const float4*>(att)[lane];
    float p = 0.0f;
    p = fmaf(lrelu(a.x + b.x), t.x, p);
    p = fmaf(lrelu(a.y + b.y), t.y, p);
    p = fmaf(lrelu(a.z + b.z), t.z, p);
    p = fmaf(lrelu(a.w + b.w), t.w, p);
    #pragma unroll
    for (int o = 16; o >= 1; o >>= 1) p += __shfl_xor_sync(0xffffffffu, p, o);
    if (lane == 0) {
        g_logits2[w] = p;
        atomicMaxFloat(g_m2 + dst, p);
    }
}

__global__ void expsum2_kernel(const int* __restrict__ ei) {
    int e = blockIdx.x * blockDim.x + threadIdx.x;
    if (e >= ET) return;
    int dst = (e < EE) ? ei[EE + e] : e - EE;
    float a = expf(g_logits2[e] - g_m2[dst]);
    g_logits2[e] = a;
    atomicAdd(g_s2 + dst, a);
}

__global__ void aggregate2_kernel(const int* __restrict__ ei) {
    int w = (blockIdx.x * blockDim.x + threadIdx.x) >> 5;
    int lane = threadIdx.x & 31;
    if (w >= ET) return;
    int src, dst;
    if (w < EE) { src = ei[w]; dst = ei[EE + w]; }
    else        { src = dst = w - EE; }
    float alpha = g_logits2[w] / g_s2[dst];
    float4 v = reinterpret_cast<const float4*>(g_xl2 + (size_t)src * DOUT)[lane];
    v.x *= alpha; v.y *= alpha; v.z *= alpha; v.w *= alpha;
    redAdd4(g_z2 + (size_t)dst * DOUT + lane * 4, v);
}

// ---------------- decoder: gathered-A GEMM + fused GELU + final dot ----------
// BM=64 (edges), BN=128 (=HID full), BK=16, 256 threads, 4x8 per thread.
__global__ void decoder_kernel(const float* __restrict__ bias2,
                               const int* __restrict__ eli,
                               const float* __restrict__ Wd1,
                               const float* __restrict__ bd1,
                               const float* __restrict__ Wd2,
                               const float* __restrict__ bd2,
                               float* __restrict__ outp) {
    constexpr int BM = 64, BN = 128, BK = 16, TM = 4, TN = 8;
    __shared__ float As[BK][BM + 4];
    __shared__ float Bs[BK][BN];

    const int tid = threadIdx.x;
    const int tx = tid % 16;
    const int ty = tid / 16;
    const int rowBase = blockIdx.x * BM;
    const int* ela = eli;
    const int* elb = eli + EL;

    float acc[TM][TN];
    #pragma unroll
    for (int i = 0; i < TM; i++)
        #pragma unroll
        for (int j = 0; j < TN; j++) acc[i][j] = 0.0f;

    for (int kk = 0; kk < 2 * DOUT; kk += BK) {
        // A tile: 64 rows x 16 k = 256 float4, one per thread (bias2 folded in)
        {
            int ar  = tid / 4;
            int akv = tid % 4;
            int r = rowBase + ar;
            float4 v = make_float4(0.f, 0.f, 0.f, 0.f);
            if (r < EL) {
                int node = (kk < DOUT) ? ela[r] : elb[r];
                int off = (kk & (DOUT - 1)) + akv * 4;
                v = ld4(g_z2 + (size_t)node * DOUT + off);
                float4 b = ld4(bias2 + off);
                v.x += b.x; v.y += b.y; v.z += b.z; v.w += b.w;
            }
            As[akv * 4 + 0][ar] = v.x;
            As[akv * 4 + 1][ar] = v.y;
            As[akv * 4 + 2][ar] = v.z;
            As[akv * 4 + 3][ar] = v.w;
        }
        // B tile: Wd1 16 x 128 = 512 float4, two per thread
        #pragma unroll
        for (int it = 0; it < 2; ++it) {
            int idx = tid + it * 256;
            int br  = idx / 32;
            int bcv = idx % 32;
            *reinterpret_cast<float4*>(&Bs[br][bcv * 4]) =
                ld4(Wd1 + (size_t)(kk + br) * BN + bcv * 4);
        }
        __syncthreads();

        #pragma unroll
        for (int k = 0; k < BK; ++k) {
            float4 ra = *reinterpret_cast<const float4*>(&As[k][ty * TM]);
            float4 rb0 = *reinterpret_cast<const float4*>(&Bs[k][tx * TN]);
            float4 rb1 = *reinterpret_cast<const float4*>(&Bs[k][tx * TN + 4]);
            float rav[TM] = {ra.x, ra.y, ra.z, ra.w};
            float rbv[TN] = {rb0.x, rb0.y, rb0.z, rb0.w, rb1.x, rb1.y, rb1.z, rb1.w};
            #pragma unroll
            for (int i = 0; i < TM; i++)
                #pragma unroll
                for (int j = 0; j < TN; j++)
                    acc[i][j] = fmaf(rav[i], rbv[j], acc[i][j]);
        }
        __syncthreads();
    }

    // epilogue: per-row p = sum_j gelu(acc + bd1) * Wd2, reduce across tx half-warp
    float4 b0 = ld4(bd1 + tx * TN);
    float4 b1 = ld4(bd1 + tx * TN + 4);
    float4 w0 = ld4(Wd2 + tx * TN);
    float4 w1 = ld4(Wd2 + tx * TN + 4);
    float bb[TN] = {b0.x, b0.y, b0.z, b0.w, b1.x, b1.y, b1.z, b1.w};
    float ww[TN] = {w0.x, w0.y, w0.z, w0.w, w1.x, w1.y, w1.z, w1.w};
    float bd2v = bd2[0];

    #pragma unroll
    for (int i = 0; i < TM; i++) {
        float p = 0.0f;
        #pragma unroll
        for (int j = 0; j < TN; j++)
            p = fmaf(gelu_tanh(acc[i][j] + bb[j]), ww[j], p);
        p += __shfl_xor_sync(0xffffffffu, p, 8);
        p += __shfl_xor_sync(0xffffffffu, p, 4);
        p += __shfl_xor_sync(0xffffffffu, p, 2);
        p += __shfl_xor_sync(0xffffffffu, p, 1);
        int r = rowBase + ty * TM + i;
        if (tx == 0 && r < EL) outp[r] = p + bd2v;
    }
}

// ---------------- host launch (kernel launches ONLY) ----------------
extern "C" void kernel_launch(void* const* d_in, const int* in_sizes, int n_in,
                              void* d_out, int out_size) {
    const float* x     = (const float*)d_in[0];
    const int*   ei    = (const int*)d_in[1];
    const int*   eli   = (const int*)d_in[2];
    const float* W_l1  = (const float*)d_in[3];
    const float* b_l1  = (const float*)d_in[4];
    const float* W_r1  = (const float*)d_in[5];
    const float* b_r1  = (const float*)d_in[6];
    const float* att1  = (const float*)d_in[7];
    const float* bias1 = (const float*)d_in[8];
    const float* W_l2  = (const float*)d_in[9];
    const float* b_l2  = (const float*)d_in[10];
    const float* W_r2  = (const float*)d_in[11];
    const float* b_r2  = (const float*)d_in[12];
    const float* att2  = (const float*)d_in[13];
    const float* bias2 = (const float*)d_in[14];
    const float* W_d1  = (const float*)d_in[15];
    const float* b_d1  = (const float*)d_in[16];
    const float* W_d2  = (const float*)d_in[17];
    const float* b_d2  = (const float*)d_in[18];
    float* outp = (float*)d_out;

    init_kernel<<<(NND * D1 + 255) / 256, 256>>>();

    const int warpBlocks = (ET * 32 + 255) / 256;   // 42500
    const int edgeBlocks = (ET + 255) / 256;        // 1329

    // layer 1 GEMMs: g_xl1 = x@W_l1+b_l1, g_xr1 = x@W_r1+b_r1
    dim3 g1(D1 / 64, (NND + 127) / 128);
    sgemm_bias_kernel<128, 64, 16, 8, 4, -1, 0><<<g1, 256>>>(x, W_l1, b_l1, NND, D1, DIN);
    sgemm_bias_kernel<128, 64, 16, 8, 4, -1, 1><<<g1, 256>>>(x, W_r1, b_r1, NND, D1, DIN);

    logits1_kernel<<<warpBlocks, 256>>>(ei, att1);
    expsum1_kernel<<<edgeBlocks, 256>>>(ei);
    aggregate1_kernel<<<warpBlocks, 256>>>(ei);

    gelu_bias_kernel<<<(NND * D1 / 4 + 255) / 256, 256>>>(bias1);

    // layer 2 GEMMs: g_xl2 = x2@W_l2+b_l2, g_xr2 = x2@W_r2+b_r2
    dim3 g2(DOUT / 64, (NND + 127) / 128);
    sgemm_bias_kernel<128, 64, 16, 8, 4, 2, 3><<<g2, 256>>>(nullptr, W_l2, b_l2, NND, DOUT, D1);
    sgemm_bias_kernel<128, 64, 16, 8, 4, 2, 4><<<g2, 256>>>(nullptr, W_r2, b_r2, NND, DOUT, D1);

    logits2_kernel<<<warpBlocks, 256>>>(ei, att2);
    expsum2_kernel<<<edgeBlocks, 256>>>(ei);
    aggregate2_kernel<<<warpBlocks, 256>>>(ei);

    // decoder (bias2 folded into gather)
    decoder_kernel<<<(EL + 63) / 64, 256>>>(bias2, eli, W_d1, b_d1, W_d2, b_d2, outp);
}

// round 5
// speedup vs baseline: 1.4483x; 1.4483x over previous
#include <cuda_runtime.h>
#include <cuda_bf16.h>
#include <cstdint>
#include <math_constants.h>

// ---------------- problem constants ----------------
#define NND   20000          // nodes
#define EE    320000         // edges
#define ET    340000         // edges + self loops
#define EL    100000         // label edges
#define DIN   256
#define DHID  128
#define DOUT  128
#define NH    4
#define D1    512            // NH*DHID
#define NEG   0.2f

// ---------------- device scratch (16B-aligned) ----------
__device__ __align__(16) float g_xl1[NND * D1];
__device__ __align__(16) float g_xr1[NND * D1];
__device__ __align__(16) float g_x2[NND * D1];     // fused layer1 output (post-gelu)
__device__ __align__(16) float g_xl2[NND * DOUT];
__device__ __align__(16) float g_xr2[NND * DOUT];
__device__ __align__(16) float g_z2[NND * DOUT];   // fused layer2 output (pre-bias2)
// CSR
__device__ int g_deg[NND];
__device__ int g_off[NND + 1];
__device__ int g_cur[NND];
__device__ int g_csr[ET];

// ---------------- helpers ----------------
__device__ __forceinline__ float4 ld4(const float* p) {
    return *reinterpret_cast<const float4*>(p);
}

__device__ __forceinline__ float gelu_tanh(float x) {
    float x3 = x * x * x;
    float t = tanhf(0.7978845608028654f * (x + 0.044715f * x3));
    return 0.5f * x * (1.0f + t);
}

__device__ __forceinline__ float lrelu(float x) {
    return x > 0.0f ? x : NEG * x;
}

// ---------------- CSR build ----------------
__global__ void deg_init_kernel() {
    int n = blockIdx.x * blockDim.x + threadIdx.x;
    if (n < NND) g_deg[n] = 1;   // self-loop
}

__global__ void deg_count_kernel(const int* __restrict__ ei) {
    int e = blockIdx.x * blockDim.x + threadIdx.x;
    if (e < EE) atomicAdd(&g_deg[ei[EE + e]], 1);
}

// single-block exclusive scan over NND (1024 threads)
__global__ void scan_kernel() {
    __shared__ int warpsum[32];
    __shared__ int carrysh;
    int tid = threadIdx.x, lane = tid & 31, wid = tid >> 5;
    if (tid == 0) carrysh = 0;
    __syncthreads();
    for (int base = 0; base < NND; base += 1024) {
        int i = base + tid;
        int v = (i < NND) ? g_deg[i] : 0;
        int x = v;
        #pragma unroll
        for (int o = 1; o < 32; o <<= 1) {
            int t = __shfl_up_sync(0xffffffffu, x, o);
            if (lane >= o) x += t;
        }
        if (lane == 31) warpsum[wid] = x;
        __syncthreads();
        if (wid == 0) {
            int y = warpsum[lane];
            #pragma unroll
            for (int o = 1; o < 32; o <<= 1) {
                int t = __shfl_up_sync(0xffffffffu, y, o);
                if (lane >= o) y += t;
            }
            warpsum[lane] = y;
        }
        __syncthreads();
        int prefix = ((wid > 0) ? warpsum[wid - 1] : 0) + carrysh;
        int excl = prefix + x - v;
        if (i < NND) g_off[i] = excl;
        __syncthreads();
        if (tid == 1023) carrysh = prefix + x;
        __syncthreads();
    }
    if (threadIdx.x == 0) g_off[NND] = carrysh;
}

__global__ void selfloop_kernel() {
    int n = blockIdx.x * blockDim.x + threadIdx.x;
    if (n < NND) {
        int o = g_off[n];
        g_csr[o] = n;
        g_cur[n] = o + 1;
    }
}

__global__ void scatter_kernel(const int* __restrict__ ei) {
    int e = blockIdx.x * blockDim.x + threadIdx.x;
    if (e >= EE) return;
    int dst = ei[EE + e];
    int p = atomicAdd(&g_cur[dst], 1);
    g_csr[p] = ei[e];
}

// ---------------- scratch selectors (device-code resolution) --------------
template<int SEL>
__device__ __forceinline__ const float* a_sel(const float* A) {
    if constexpr (SEL == 2) return g_x2;
    else return A;
}
template<int SEL>
__device__ __forceinline__ float* c_sel() {
    if constexpr (SEL == 0) return g_xl1;
    else if constexpr (SEL == 1) return g_xr1;
    else if constexpr (SEL == 3) return g_xl2;
    else return g_xr2;
}

// ---------------- SGEMM: C[M,N] = A[M,K] @ B[K,N] + bias[N] ----------------
template<int BM, int BN, int BK, int TM, int TN, int ASEL, int CSEL>
__global__ void sgemm_bias_kernel(const float* __restrict__ Ain,
                                  const float* __restrict__ B,
                                  const float* __restrict__ bias,
                                  int M, int N, int K) {
    constexpr int THREADS = (BM * BN) / (TM * TN);   // 256
    const float* __restrict__ A = a_sel<ASEL>(Ain);
    float* __restrict__ C = c_sel<CSEL>();

    __shared__ float As[BK][BM + 4];
    __shared__ float Bs[BK][BN];

    const int tid = threadIdx.x;
    const int tx = tid % (BN / TN);
    const int ty = tid / (BN / TN);
    const int rowBase = blockIdx.y * BM;
    const int colBase = blockIdx.x * BN;

    float acc[TM][TN];
    #pragma unroll
    for (int i = 0; i < TM; i++)
        #pragma unroll
        for (int j = 0; j < TN; j++) acc[i][j] = 0.0f;

    for (int kk = 0; kk < K; kk += BK) {
        #pragma unroll
        for (int it = 0; it < (BM * BK) / (4 * THREADS); ++it) {
            int idx = tid + it * THREADS;
            int ar  = idx / (BK / 4);
            int akv = idx % (BK / 4);
            int grow = rowBase + ar;
            float4 v = (grow < M) ? ld4(A + (size_t)grow * K + kk + akv * 4)
                                  : make_float4(0.f, 0.f, 0.f, 0.f);
            As[akv * 4 + 0][ar] = v.x;
            As[akv * 4 + 1][ar] = v.y;
            As[akv * 4 + 2][ar] = v.z;
            As[akv * 4 + 3][ar] = v.w;
        }
        #pragma unroll
        for (int it = 0; it < (BK * BN) / (4 * THREADS); ++it) {
            int idx = tid + it * THREADS;
            int br  = idx / (BN / 4);
            int bcv = idx % (BN / 4);
            *reinterpret_cast<float4*>(&Bs[br][bcv * 4]) =
                ld4(B + (size_t)(kk + br) * N + colBase + bcv * 4);
        }
        __syncthreads();

        #pragma unroll
        for (int k = 0; k < BK; ++k) {
            float4 ra0 = *reinterpret_cast<const float4*>(&As[k][ty * TM]);
            float4 ra1 = *reinterpret_cast<const float4*>(&As[k][ty * TM + 4]);
            float4 rb  = *reinterpret_cast<const float4*>(&Bs[k][tx * TN]);
            float ra[TM] = {ra0.x, ra0.y, ra0.z, ra0.w, ra1.x, ra1.y, ra1.z, ra1.w};
            float rbv[TN] = {rb.x, rb.y, rb.z, rb.w};
            #pragma unroll
            for (int i = 0; i < TM; i++)
                #pragma unroll
                for (int j = 0; j < TN; j++)
                    acc[i][j] = fmaf(ra[i], rbv[j], acc[i][j]);
        }
        __syncthreads();
    }

    float4 bv = ld4(bias + colBase + tx * TN);
    #pragma unroll
    for (int i = 0; i < TM; i++) {
        int r = rowBase + ty * TM + i;
        if (r < M) {
            float4 o = make_float4(acc[i][0] + bv.x, acc[i][1] + bv.y,
                                   acc[i][2] + bv.z, acc[i][3] + bv.w);
            *reinterpret_cast<float4*>(C + (size_t)r * N + colBase + tx * TN) = o;
        }
    }
}

// ---------------- fused GAT layer 1 (H=4, C=128, online softmax) -----------
// warp per destination node; lane owns 16 contiguous floats; head = lane>>3.
// Epilogue fuses +bias1 and GELU, writes g_x2 directly.
__global__ __launch_bounds__(256) void fused_gat1_kernel(
        const float* __restrict__ att, const float* __restrict__ bias1) {
    int n = (blockIdx.x * blockDim.x + threadIdx.x) >> 5;
    int lane = threadIdx.x & 31;
    if (n >= NND) return;

    const float4* pr = reinterpret_cast<const float4*>(g_xr1 + (size_t)n * D1) + lane * 4;
    const float4* pt = reinterpret_cast<const float4*>(att) + lane * 4;
    float4 br[4], at[4];
    #pragma unroll
    for (int i = 0; i < 4; i++) { br[i] = pr[i]; at[i] = pt[i]; }

    float m = -CUDART_INF_F, s = 0.0f;
    float4 acc[4];
    #pragma unroll
    for (int i = 0; i < 4; i++) acc[i] = make_float4(0.f, 0.f, 0.f, 0.f);

    int e0 = g_off[n], e1 = g_off[n + 1];
    for (int e = e0; e < e1; ++e) {
        int src = g_csr[e];
        const float4* pa = reinterpret_cast<const float4*>(g_xl1 + (size_t)src * D1) + lane * 4;
        float4 a[4];
        #pragma unroll
        for (int i = 0; i < 4; i++) a[i] = pa[i];

        float p = 0.0f;
        #pragma unroll
        for (int i = 0; i < 4; i++) {
            p = fmaf(lrelu(a[i].x + br[i].x), at[i].x, p);
            p = fmaf(lrelu(a[i].y + br[i].y), at[i].y, p);
            p = fmaf(lrelu(a[i].z + br[i].z), at[i].z, p);
            p = fmaf(lrelu(a[i].w + br[i].w), at[i].w, p);
        }
        // reduce within 8-lane head group
        p += __shfl_xor_sync(0xffffffffu, p, 4);
        p += __shfl_xor_sync(0xffffffffu, p, 2);
        p += __shfl_xor_sync(0xffffffffu, p, 1);

        float mn = fmaxf(m, p);
        float so = expf(m - mn);      // 0 on first edge (m = -inf)
        float wg = expf(p - mn);
        s = s * so + wg;
        #pragma unroll
        for (int i = 0; i < 4; i++) {
            acc[i].x = acc[i].x * so + wg * a[i].x;
            acc[i].y = acc[i].y * so + wg * a[i].y;
            acc[i].z = acc[i].z * so + wg * a[i].z;
            acc[i].w = acc[i].w * so + wg * a[i].w;
        }
        m = mn;
    }

    float inv = 1.0f / s;
    const float4* pb = reinterpret_cast<const float4*>(bias1) + lane * 4;
    float4* po = reinterpret_cast<float4*>(g_x2 + (size_t)n * D1) + lane * 4;
    #pragma unroll
    for (int i = 0; i < 4; i++) {
        float4 b = pb[i];
        float4 o;
        o.x = gelu_tanh(acc[i].x * inv + b.x);
        o.y = gelu_tanh(acc[i].y * inv + b.y);
        o.z = gelu_tanh(acc[i].z * inv + b.z);
        o.w = gelu_tanh(acc[i].w * inv + b.w);
        po[i] = o;
    }
}

// ---------------- fused GAT layer 2 (H=1, C=128, online softmax) -----------
// warp per destination node; lane owns 4 floats. Writes g_z2 (bias2 added in decoder).
__global__ __launch_bounds__(256) void fused_gat2_kernel(const float* __restrict__ att) {
    int n = (blockIdx.x * blockDim.x + threadIdx.x) >> 5;
    int lane = threadIdx.x & 31;
    if (n >= NND) return;

    float4 br = reinterpret_cast<const float4*>(g_xr2 + (size_t)n * DOUT)[lane];
    float4 at = reinterpret_cast<const float4*>(att)[lane];

    float m = -CUDART_INF_F, s = 0.0f;
    float4 acc = make_float4(0.f, 0.f, 0.f, 0.f);

    int e0 = g_off[n], e1 = g_off[n + 1];
    for (int e = e0; e < e1; ++e) {
        int src = g_csr[e];
        float4 a = reinterpret_cast<const float4*>(g_xl2 + (size_t)src * DOUT)[lane];
        float p = 0.0f;
        p = fmaf(lrelu(a.x + br.x), at.x, p);
        p = fmaf(lrelu(a.y + br.y), at.y, p);
        p = fmaf(lrelu(a.z + br.z), at.z, p);
        p = fmaf(lrelu(a.w + br.w), at.w, p);
        #pragma unroll
        for (int o = 16; o >= 1; o >>= 1) p += __shfl_xor_sync(0xffffffffu, p, o);

        float mn = fmaxf(m, p);
        float so = expf(m - mn);
        float wg = expf(p - mn);
        s = s * so + wg;
        acc.x = acc.x * so + wg * a.x;
        acc.y = acc.y * so + wg * a.y;
        acc.z = acc.z * so + wg * a.z;
        acc.w = acc.w * so + wg * a.w;
        m = mn;
    }

    float inv = 1.0f / s;
    float4 o = make_float4(acc.x * inv, acc.y * inv, acc.z * inv, acc.w * inv);
    reinterpret_cast<float4*>(g_z2 + (size_t)n * DOUT)[lane] = o;
}

// ---------------- decoder: gathered-A GEMM + fused GELU + final dot ----------
__global__ void decoder_kernel(const float* __restrict__ bias2,
                               const int* __restrict__ eli,
                               const float* __restrict__ Wd1,
                               const float* __restrict__ bd1,
                               const float* __restrict__ Wd2,
                               const float* __restrict__ bd2,
                               float* __restrict__ outp) {
    constexpr int BM = 64, BN = 128, BK = 16, TM = 4, TN = 8;
    __shared__ float As[BK][BM + 4];
    __shared__ float Bs[BK][BN];

    const int tid = threadIdx.x;
    const int tx = tid % 16;
    const int ty = tid / 16;
    const int rowBase = blockIdx.x * BM;
    const int* ela = eli;
    const int* elb = eli + EL;

    float acc[TM][TN];
    #pragma unroll
    for (int i = 0; i < TM; i++)
        #pragma unroll
        for (int j = 0; j < TN; j++) acc[i][j] = 0.0f;

    for (int kk = 0; kk < 2 * DOUT; kk += BK) {
        {
            int ar  = tid / 4;
            int akv = tid % 4;
            int r = rowBase + ar;
            float4 v = make_float4(0.f, 0.f, 0.f, 0.f);
            if (r < EL) {
                int node = (kk < DOUT) ? ela[r] : elb[r];
                int off = (kk & (DOUT - 1)) + akv * 4;
                v = ld4(g_z2 + (size_t)node * DOUT + off);
                float4 b = ld4(bias2 + off);
                v.x += b.x; v.y += b.y; v.z += b.z; v.w += b.w;
            }
            As[akv * 4 + 0][ar] = v.x;
            As[akv * 4 + 1][ar] = v.y;
            As[akv * 4 + 2][ar] = v.z;
            As[akv * 4 + 3][ar] = v.w;
        }
        #pragma unroll
        for (int it = 0; it < 2; ++it) {
            int idx = tid + it * 256;
            int br  = idx / 32;
            int bcv = idx % 32;
            *reinterpret_cast<float4*>(&Bs[br][bcv * 4]) =
                ld4(Wd1 + (size_t)(kk + br) * BN + bcv * 4);
        }
        __syncthreads();

        #pragma unroll
        for (int k = 0; k < BK; ++k) {
            float4 ra = *reinterpret_cast<const float4*>(&As[k][ty * TM]);
            float4 rb0 = *reinterpret_cast<const float4*>(&Bs[k][tx * TN]);
            float4 rb1 = *reinterpret_cast<const float4*>(&Bs[k][tx * TN + 4]);
            float rav[TM] = {ra.x, ra.y, ra.z, ra.w};
            float rbv[TN] = {rb0.x, rb0.y, rb0.z, rb0.w, rb1.x, rb1.y, rb1.z, rb1.w};
            #pragma unroll
            for (int i = 0; i < TM; i++)
                #pragma unroll
                for (int j = 0; j < TN; j++)
                    acc[i][j] = fmaf(rav[i], rbv[j], acc[i][j]);
        }
        __syncthreads();
    }

    float4 b0 = ld4(bd1 + tx * TN);
    float4 b1 = ld4(bd1 + tx * TN + 4);
    float4 w0 = ld4(Wd2 + tx * TN);
    float4 w1 = ld4(Wd2 + tx * TN + 4);
    float bb[TN] = {b0.x, b0.y, b0.z, b0.w, b1.x, b1.y, b1.z, b1.w};
    float ww[TN] = {w0.x, w0.y, w0.z, w0.w, w1.x, w1.y, w1.z, w1.w};
    float bd2v = bd2[0];

    #pragma unroll
    for (int i = 0; i < TM; i++) {
        float p = 0.0f;
        #pragma unroll
        for (int j = 0; j < TN; j++)
            p = fmaf(gelu_tanh(acc[i][j] + bb[j]), ww[j], p);
        p += __shfl_xor_sync(0xffffffffu, p, 8);
        p += __shfl_xor_sync(0xffffffffu, p, 4);
        p += __shfl_xor_sync(0xffffffffu, p, 2);
        p += __shfl_xor_sync(0xffffffffu, p, 1);
        int r = rowBase + ty * TM + i;
        if (tx == 0 && r < EL) outp[r] = p + bd2v;
    }
}

// ---------------- host launch (kernel launches ONLY) ----------------
extern "C" void kernel_launch(void* const* d_in, const int* in_sizes, int n_in,
                              void* d_out, int out_size) {
    const float* x     = (const float*)d_in[0];
    const int*   ei    = (const int*)d_in[1];
    const int*   eli   = (const int*)d_in[2];
    const float* W_l1  = (const float*)d_in[3];
    const float* b_l1  = (const float*)d_in[4];
    const float* W_r1  = (const float*)d_in[5];
    const float* b_r1  = (const float*)d_in[6];
    const float* att1  = (const float*)d_in[7];
    const float* bias1 = (const float*)d_in[8];
    const float* W_l2  = (const float*)d_in[9];
    const float* b_l2  = (const float*)d_in[10];
    const float* W_r2  = (const float*)d_in[11];
    const float* b_r2  = (const float*)d_in[12];
    const float* att2  = (const float*)d_in[13];
    const float* bias2 = (const float*)d_in[14];
    const float* W_d1  = (const float*)d_in[15];
    const float* b_d1  = (const float*)d_in[16];
    const float* W_d2  = (const float*)d_in[17];
    const float* b_d2  = (const float*)d_in[18];
    float* outp = (float*)d_out;

    // ---- CSR build (dst-grouped adjacency incl. self loops) ----
    deg_init_kernel<<<(NND + 255) / 256, 256>>>();
    deg_count_kernel<<<(EE + 255) / 256, 256>>>(ei);
    scan_kernel<<<1, 1024>>>();
    selfloop_kernel<<<(NND + 255) / 256, 256>>>();
    scatter_kernel<<<(EE + 255) / 256, 256>>>(ei);

    const int nodeWarpBlocks = (NND * 32 + 255) / 256;   // warp per node

    // ---- layer 1 ----
    dim3 g1(D1 / 64, (NND + 127) / 128);
    sgemm_bias_kernel<128, 64, 16, 8, 4, -1, 0><<<g1, 256>>>(x, W_l1, b_l1, NND, D1, DIN);
    sgemm_bias_kernel<128, 64, 16, 8, 4, -1, 1><<<g1, 256>>>(x, W_r1, b_r1, NND, D1, DIN);
    fused_gat1_kernel<<<nodeWarpBlocks, 256>>>(att1, bias1);

    // ---- layer 2 ----
    dim3 g2(DOUT / 64, (NND + 127) / 128);
    sgemm_bias_kernel<128, 64, 16, 8, 4, 2, 3><<<g2, 256>>>(nullptr, W_l2, b_l2, NND, DOUT, D1);
    sgemm_bias_kernel<128, 64, 16, 8, 4, 2, 4><<<g2, 256>>>(nullptr, W_r2, b_r2, NND, DOUT, D1);
    fused_gat2_kernel<<<nodeWarpBlocks, 256>>>(att2);

    // ---- decoder ----
    decoder_kernel<<<(EL + 63) / 64, 256>>>(bias2, eli, W_d1, b_d1, W_d2, b_d2, outp);
}